// round 1
// baseline (speedup 1.0000x reference)
#include <cuda_runtime.h>
#include <cuda_bf16.h>

#define HID   1024
#define INTERD 2816
#define BB    4
#define NTOK  32768   // B * N = 4 * 8192
#define ODIM  1024

// ---------------- scratch (static device globals; no allocs) ----------------
__device__ float g_sc[BB * HID];
__device__ float g_h[BB * HID];
__device__ float g_gy[BB * 2 * INTERD];
__device__ float g_u[BB * INTERD];
__device__ float g_z[BB * HID];
__device__ float g_o[BB * 2 * HID];
__device__ float g_mod[BB * 2 * HID];
__device__ float g_part[1024];
__device__ float g_ws[2];                       // [0] = scale (1/clip(mean|w|)), [1] = clip(mean|w|)
__device__ __align__(16) __nv_bfloat16 g_wq[(long)ODIM * HID];     // ternary weights as bf16
__device__ __align__(16) __nv_bfloat16 g_q[(long)NTOK * HID];      // quantized activations (ints) as bf16
__device__ float g_arecip[NTOK];                // per-token amax/127 * mean|w|

__device__ __forceinline__ float silu_f(float v) { return v / (1.f + expf(-v)); }

// ---------------- tiny elementwise kernels ----------------
__global__ void silu_c_kernel(const float* __restrict__ c) {
    int i = blockIdx.x * 256 + threadIdx.x;
    if (i < BB * HID) g_sc[i] = silu_f(c[i]);
}

__global__ void gateact_kernel() {
    int i = blockIdx.x * 256 + threadIdx.x;
    if (i < BB * INTERD) {
        int b = i / INTERD, j = i - b * INTERD;
        float g = g_gy[b * 2 * INTERD + j];
        float y = g_gy[b * 2 * INTERD + INTERD + j];
        g_u[i] = silu_f(g) * y;
    }
}

// out[b,d] = sum_k A[b,k] * W[d,k] (+ bias[d]); one warp per output element
__global__ void gemm4_kernel(const float* __restrict__ A, const float* __restrict__ W,
                             const float* __restrict__ bias, float* __restrict__ out,
                             int K, int D) {
    int warp = threadIdx.x >> 5, lane = threadIdx.x & 31;
    int idx = blockIdx.x * 8 + warp;
    if (idx >= 4 * D) return;
    int b = idx / D, d = idx - b * D;
    const float* a = A + (long)b * K;
    const float* w = W + (long)d * K;
    float s = 0.f;
#pragma unroll 8
    for (int k = lane; k < K; k += 32) s += a[k] * w[k];
#pragma unroll
    for (int o = 16; o; o >>= 1) s += __shfl_xor_sync(0xffffffffu, s, o);
    if (lane == 0) out[idx] = s + (bias ? bias[d] : 0.f);
}

// in-place rmsnorm of g_o rows (len 2048), eps 1e-6, weight w_norm
__global__ void rms4_kernel(const float* __restrict__ w_norm) {
    __shared__ float sm[256];
    int b = blockIdx.x, tid = threadIdx.x;
    float* o = g_o + b * 2048;
    float s = 0.f;
    for (int i = tid; i < 2048; i += 256) { float v = o[i]; s += v * v; }
    sm[tid] = s; __syncthreads();
    for (int st = 128; st > 0; st >>= 1) { if (tid < st) sm[tid] += sm[tid + st]; __syncthreads(); }
    float rstd = rsqrtf(sm[0] * (1.f / 2048.f) + 1e-6f);
    for (int i = tid; i < 2048; i += 256) o[i] = o[i] * rstd * w_norm[i];
}

// ---------------- weight quant (deterministic reduction) ----------------
__global__ void wabs_partial_kernel(const float* __restrict__ w) {
    __shared__ float sm[256];
    int b = blockIdx.x, tid = threadIdx.x;
    const float* p = w + (long)b * 1024;
    float s = 0.f;
    for (int i = tid; i < 1024; i += 256) s += fabsf(p[i]);
    sm[tid] = s; __syncthreads();
    for (int st = 128; st > 0; st >>= 1) { if (tid < st) sm[tid] += sm[tid + st]; __syncthreads(); }
    if (tid == 0) g_part[b] = sm[0];
}

__global__ void wabs_final_kernel() {
    __shared__ float sm[256];
    int tid = threadIdx.x;
    float s = g_part[tid] + g_part[tid + 256] + g_part[tid + 512] + g_part[tid + 768];
    sm[tid] = s; __syncthreads();
    for (int st = 128; st > 0; st >>= 1) { if (tid < st) sm[tid] += sm[tid + st]; __syncthreads(); }
    if (tid == 0) {
        float mean = sm[0] * (1.f / (1024.f * 1024.f));
        float m = fmaxf(mean, 1e-5f);
        g_ws[0] = 1.f / m;   // scale
        g_ws[1] = m;         // 1/scale
    }
}

__global__ void wquant_kernel(const float* __restrict__ w) {
    int i = blockIdx.x * 256 + threadIdx.x;
    if (i < ODIM * HID) {
        float s = g_ws[0];
        float v = fminf(fmaxf(rintf(w[i] * s), -1.f), 1.f);
        g_wq[i] = __float2bfloat16(v);
    }
}

// ---------------- activation pipeline: LN -> modulate -> RMSNorm -> quant ----------------
__global__ void aq_kernel(const float* __restrict__ x, const float* __restrict__ wbn) {
    __shared__ float sm[256];
    __shared__ float sm2[256];
    int t = blockIdx.x, tid = threadIdx.x;
    int b = t >> 13;                    // 8192 tokens per batch
    const float* xr = x + (long)t * HID;
    const float* mod = g_mod + b * 2048; // [0:1024) shift, [1024:2048) scale
    float v[4];
    float s = 0.f, s2 = 0.f;
#pragma unroll
    for (int i = 0; i < 4; i++) {
        float xv = xr[tid + i * 256];
        v[i] = xv; s += xv; s2 += xv * xv;
    }
    sm[tid] = s; sm2[tid] = s2; __syncthreads();
    for (int st = 128; st > 0; st >>= 1) {
        if (tid < st) { sm[tid] += sm[tid + st]; sm2[tid] += sm2[tid + st]; }
        __syncthreads();
    }
    float mean = sm[0] * (1.f / HID);
    float var = sm2[0] * (1.f / HID) - mean * mean;
    float rstd = rsqrtf(var + 1e-6f);
    __syncthreads();

    float ms = 0.f;
#pragma unroll
    for (int i = 0; i < 4; i++) {
        int h = tid + i * 256;
        float xm = (v[i] - mean) * rstd * (1.f + mod[1024 + h]) + mod[h];
        v[i] = xm; ms += xm * xm;
    }
    sm[tid] = ms; __syncthreads();
    for (int st = 128; st > 0; st >>= 1) { if (tid < st) sm[tid] += sm[tid + st]; __syncthreads(); }
    float rr = rsqrtf(sm[0] * (1.f / HID) + 1e-8f);
    __syncthreads();

    float amax = 0.f;
#pragma unroll
    for (int i = 0; i < 4; i++) {
        int h = tid + i * 256;
        float q = v[i] * rr * wbn[h];
        v[i] = q;
        amax = fmaxf(amax, fabsf(q));
    }
    sm[tid] = amax; __syncthreads();
    for (int st = 128; st > 0; st >>= 1) { if (tid < st) sm[tid] = fmaxf(sm[tid], sm[tid + st]); __syncthreads(); }
    float am = fmaxf(sm[0], 1e-5f);
    float sa = 127.f / am;
    __nv_bfloat16* qp = g_q + (long)t * HID;
#pragma unroll
    for (int i = 0; i < 4; i++) {
        int h = tid + i * 256;
        float qv = fminf(fmaxf(rintf(v[i] * sa), -128.f), 127.f);
        qp[h] = __float2bfloat16(qv);
    }
    if (tid == 0) g_arecip[t] = am * (1.f / 127.f) * g_ws[1];
}

// ---------------- main GEMM: [32768,1024] x [1024,1024]^T, bf16 MMA, exact int math ----------------
__device__ __forceinline__ void cp16(void* s, const void* g) {
    unsigned sa = (unsigned)__cvta_generic_to_shared(s);
    asm volatile("cp.async.cg.shared.global [%0], [%1], 16;\n" :: "r"(sa), "l"(g));
}

#define GLDS 40   // padded row stride in bf16 (conflict-free fragment loads)

__global__ void __launch_bounds__(256, 2) bitgemm_kernel(const float* __restrict__ bias,
                                                         float* __restrict__ out) {
    __shared__ __align__(16) __nv_bfloat16 As[2][128 * GLDS];
    __shared__ __align__(16) __nv_bfloat16 Bs[2][128 * GLDS];
    const int tid = threadIdx.x;
    const int lane = tid & 31, warp = tid >> 5;
    const int wm = warp >> 1, wn = warp & 1;      // 4x2 warp grid: 32 rows x 64 cols per warp
    const int mtile = blockIdx.y, ntile = blockIdx.x;
    const long arow0 = (long)mtile * 128;
    const int brow0 = ntile * 128;
    const int g = lane >> 2, tg = lane & 3;

    float acc[2][8][4];
#pragma unroll
    for (int i = 0; i < 2; i++)
#pragma unroll
        for (int j = 0; j < 8; j++)
#pragma unroll
            for (int r = 0; r < 4; r++) acc[i][j][r] = 0.f;

    // prologue load, tile 0
    {
#pragma unroll
        for (int j = 0; j < 2; j++) {
            int cidx = tid + 256 * j;
            int r = cidx >> 2; int kc = (cidx & 3) * 8;
            cp16(&As[0][r * GLDS + kc], g_q + (arow0 + r) * HID + kc);
            cp16(&Bs[0][r * GLDS + kc], g_wq + (long)(brow0 + r) * HID + kc);
        }
        asm volatile("cp.async.commit_group;\n");
    }

#pragma unroll 1
    for (int kt = 0; kt < 32; kt++) {
        if (kt < 31) {
            int k0 = (kt + 1) * 32;
            int stage = (kt + 1) & 1;
#pragma unroll
            for (int j = 0; j < 2; j++) {
                int cidx = tid + 256 * j;
                int r = cidx >> 2; int kc = (cidx & 3) * 8;
                cp16(&As[stage][r * GLDS + kc], g_q + (arow0 + r) * HID + k0 + kc);
                cp16(&Bs[stage][r * GLDS + kc], g_wq + (long)(brow0 + r) * HID + k0 + kc);
            }
            asm volatile("cp.async.commit_group;\n");
            asm volatile("cp.async.wait_group 1;\n");
        } else {
            asm volatile("cp.async.wait_group 0;\n");
        }
        __syncthreads();

        const __nv_bfloat16* Ab = As[kt & 1];
        const __nv_bfloat16* Bb = Bs[kt & 1];
#pragma unroll
        for (int ks = 0; ks < 2; ks++) {
            const int kb = ks * 16;
            unsigned afr[2][4];
#pragma unroll
            for (int i = 0; i < 2; i++) {
                int r = wm * 32 + i * 16;
                afr[i][0] = *(const unsigned*)(Ab + (r + g) * GLDS + kb + 2 * tg);
                afr[i][1] = *(const unsigned*)(Ab + (r + g + 8) * GLDS + kb + 2 * tg);
                afr[i][2] = *(const unsigned*)(Ab + (r + g) * GLDS + kb + 2 * tg + 8);
                afr[i][3] = *(const unsigned*)(Ab + (r + g + 8) * GLDS + kb + 2 * tg + 8);
            }
#pragma unroll
            for (int j = 0; j < 8; j++) {
                int nrow = wn * 64 + j * 8 + g;
                unsigned b0 = *(const unsigned*)(Bb + nrow * GLDS + kb + 2 * tg);
                unsigned b1 = *(const unsigned*)(Bb + nrow * GLDS + kb + 2 * tg + 8);
#pragma unroll
                for (int i = 0; i < 2; i++) {
                    asm volatile(
                        "mma.sync.aligned.m16n8k16.row.col.f32.bf16.bf16.f32 "
                        "{%0,%1,%2,%3}, {%4,%5,%6,%7}, {%8,%9}, {%0,%1,%2,%3};"
                        : "+f"(acc[i][j][0]), "+f"(acc[i][j][1]),
                          "+f"(acc[i][j][2]), "+f"(acc[i][j][3])
                        : "r"(afr[i][0]), "r"(afr[i][1]), "r"(afr[i][2]), "r"(afr[i][3]),
                          "r"(b0), "r"(b1));
                }
            }
        }
        __syncthreads();
    }

    // epilogue: dequant per token + bias
#pragma unroll
    for (int i = 0; i < 2; i++) {
        long row = arow0 + wm * 32 + i * 16 + g;
        float r0 = g_arecip[row];
        float r1 = g_arecip[row + 8];
#pragma unroll
        for (int j = 0; j < 8; j++) {
            int col = brow0 + wn * 64 + j * 8 + 2 * tg;
            float b0v = bias[col], b1v = bias[col + 1];
            out[row * ODIM + col]         = acc[i][j][0] * r0 + b0v;
            out[row * ODIM + col + 1]     = acc[i][j][1] * r0 + b1v;
            out[(row + 8) * ODIM + col]   = acc[i][j][2] * r1 + b0v;
            out[(row + 8) * ODIM + col + 1] = acc[i][j][3] * r1 + b1v;
        }
    }
}

// ---------------- launch ----------------
extern "C" void kernel_launch(void* const* d_in, const int* in_sizes, int n_in,
                              void* d_out, int out_size) {
    const float* x        = (const float*)d_in[0];
    const float* c        = (const float*)d_in[1];
    const float* w_input  = (const float*)d_in[2];
    const float* w_gate   = (const float*)d_in[3];
    const float* w_down   = (const float*)d_in[4];
    const float* w_output = (const float*)d_in[5];
    const float* b_output = (const float*)d_in[6];
    const float* w_norm   = (const float*)d_in[7];
    const float* w_outp   = (const float*)d_in[8];
    const float* b_outp   = (const float*)d_in[9];
    const float* w_bit    = (const float*)d_in[10];
    const float* b_bit    = (const float*)d_in[11];
    const float* w_bn     = (const float*)d_in[12];
    float* out = (float*)d_out;

    // scratch symbol addresses (host-visible pointers into device globals)
    float *p_sc, *p_h, *p_gy, *p_u, *p_z, *p_o, *p_mod;
    cudaGetSymbolAddress((void**)&p_sc,  g_sc);
    cudaGetSymbolAddress((void**)&p_h,   g_h);
    cudaGetSymbolAddress((void**)&p_gy,  g_gy);
    cudaGetSymbolAddress((void**)&p_u,   g_u);
    cudaGetSymbolAddress((void**)&p_z,   g_z);
    cudaGetSymbolAddress((void**)&p_o,   g_o);
    cudaGetSymbolAddress((void**)&p_mod, g_mod);

    // --- weight quant path (independent) ---
    wabs_partial_kernel<<<1024, 256>>>(w_bit);
    wabs_final_kernel<<<1, 256>>>();
    wquant_kernel<<<(ODIM * HID) / 256, 256>>>(w_bit);

    // --- modulation chain (B=4) ---
    silu_c_kernel<<<16, 256>>>(c);
    gemm4_kernel<<<512, 256>>>(p_sc, w_input, nullptr, p_h, HID, HID);        // h [4,1024]
    gemm4_kernel<<<2816, 256>>>(p_h, w_gate, nullptr, p_gy, HID, 2 * INTERD); // gy [4,5632]
    gateact_kernel<<<44, 256>>>();                                            // u [4,2816]
    gemm4_kernel<<<512, 256>>>(p_u, w_down, nullptr, p_z, INTERD, HID);       // z [4,1024]
    gemm4_kernel<<<1024, 256>>>(p_z, w_output, b_output, p_o, HID, 2 * HID);  // o [4,2048]
    rms4_kernel<<<4, 256>>>(w_norm);
    gemm4_kernel<<<1024, 256>>>(p_o, w_outp, b_outp, p_mod, 2 * HID, 2 * HID); // mod [4,2048]

    // --- per-token normalize + quantize ---
    aq_kernel<<<NTOK, 256>>>(x, w_bn);

    // --- main GEMM + dequant epilogue ---
    dim3 ggrid(8, 256);   // n-tiles fastest -> 8 column tiles of one m-tile co-resident (L2 A reuse)
    bitgemm_kernel<<<ggrid, 256>>>(b_bit, out);
}